// round 11
// baseline (speedup 1.0000x reference)
#include <cuda_runtime.h>
#include <cstdint>

// ScalableCritic on GB300 — round 10 (byte-identical resubmit; broker timed
// out on R2/R4–R10 before the FFMA2 candidate ever ran):
//   score[b] = lrelu(concat(gmax_b, cond_b) @ W3 + b3) @ W4 + b4
//   gmax_b   = segmented max over points of lrelu(lrelu([mu,cond]@W1+b1)@W2+b2)
//
// Kernel 1: per-batch lower_bound offsets (batch_index is sorted).
// Kernel 2: one block per batch, 128 threads; thread j owns layer-2 column j.
//           h1 tile stored point-PAIR-packed (float2) per column so the
//           64->128 layer runs on FFMA2 (fma.rn.f32x2): 2 FMAs/instr.

#define TPB  128
#define TILE 32            // points per tile
#define NPAIR (TILE / 2)   // 16 packed point-pairs

typedef unsigned int       u32;
typedef unsigned long long u64;

__device__ int g_segoff[65537];   // supports B up to 65536

__global__ void segoff_kernel(const int* __restrict__ idx, int n, int B) {
    int b = blockIdx.x * blockDim.x + threadIdx.x;
    if (b > B) return;
    int lo = 0, hi = n;
    while (lo < hi) {                     // first i with idx[i] >= b
        int mid = (lo + hi) >> 1;
        if (idx[mid] < b) lo = mid + 1; else hi = mid;
    }
    g_segoff[b] = lo;
}

__device__ __forceinline__ float lrelu(float x) {
    return fmaxf(x, 0.2f * x);            // exact for slope 0.2 < 1
}

__device__ __forceinline__ u64 pack2(float lo, float hi) {
    u64 d;
    asm("mov.b64 %0, {%1, %2};" : "=l"(d) : "f"(lo), "f"(hi));
    return d;
}
__device__ __forceinline__ void unpack2(u64 v, float& lo, float& hi) {
    asm("mov.b64 {%0, %1}, %2;" : "=f"(lo), "=f"(hi) : "l"(v));
}
__device__ __forceinline__ u64 ffma2(u64 a, u64 b, u64 c) {
    u64 d;
    asm("fma.rn.f32x2 %0, %1, %2, %3;" : "=l"(d) : "l"(a), "l"(b), "l"(c));
    return d;
}
__device__ __forceinline__ u32 saddr(const void* p) {
    u32 a;
    asm("{.reg .u64 t; cvta.to.shared.u64 t, %1; cvt.u32.u64 %0, t;}"
        : "=r"(a) : "l"(p));
    return a;
}

__global__ __launch_bounds__(TPB, 4)
void critic_kernel(const float* __restrict__ muons,
                   const float* __restrict__ cond,
                   const float* __restrict__ W1, const float* __restrict__ b1,
                   const float* __restrict__ W2, const float* __restrict__ b2,
                   const float* __restrict__ W3, const float* __restrict__ b3,
                   const float* __restrict__ W4, const float* __restrict__ b4,
                   float* __restrict__ out)
{
    const int b = blockIdx.x;
    const int j = threadIdx.x;            // 0..127: output column of layer 2

    __shared__ __align__(16) u64 h1t[64 * NPAIR]; // [k][pair] packed points
    __shared__ float sW1[192];            // W1 rows 0..2 (muon part), [f*64+k]
    __shared__ float scpre[64];           // b1 + cond_b @ W1[3:7]
    __shared__ float sW2[64 * 128];       // W2 row-major [k*128+j]  (32 KB)
    __shared__ float smu[TILE * 3];       // staged muons for current tile
    __shared__ float din[132];            // decision input
    __shared__ float wsum[4];

    float c0 = cond[b * 4 + 0], c1 = cond[b * 4 + 1];
    float c2 = cond[b * 4 + 2], c3 = cond[b * 4 + 3];

    if (j < 64) {
        sW1[j]       = W1[0 * 64 + j];
        sW1[64 + j]  = W1[1 * 64 + j];
        sW1[128 + j] = W1[2 * 64 + j];
        float p = b1[j];
        p = fmaf(c0, W1[3 * 64 + j], p);
        p = fmaf(c1, W1[4 * 64 + j], p);
        p = fmaf(c2, W1[5 * 64 + j], p);
        p = fmaf(c3, W1[6 * 64 + j], p);
        scpre[j] = p;
    }
    // Stage W2 into smem (coalesced, 64 rows of 128).
#pragma unroll
    for (int r = 0; r < 64; r++) sW2[r * 128 + j] = W2[r * 128 + j];

    const float b2j = b2[j];
    __syncthreads();

    const u32 hb = saddr(h1t);
    const u32 wb = saddr(sW2) + j * 4;

    const int s = g_segoff[b];
    const int e = g_segoff[b + 1];
    float amax = -1.0e9f;                 // scatter-amax baseline

    for (int base = s; base < e; base += TILE) {
        const int cnt = min(TILE, e - base);

        // Stage muons for this tile (coalesced).
        if (j < cnt * 3) smu[j] = muons[base * 3 + j];
        __syncthreads();

        // Producer: h1t[k][i] = { lrelu(h1[2i][k]), lrelu(h1[2i+1][k]) }
#pragma unroll
        for (int it = 0; it < (64 * NPAIR) / TPB; it++) {
            int v = it * TPB + j;         // 0..1023
            int k = v >> 4, i = v & (NPAIR - 1);
            int p0 = 2 * i, p1 = p0 + 1;
            float w0 = sW1[k], w1 = sW1[64 + k], w2v = sW1[128 + k];
            float cp = scpre[k];
            float h0 = 0.f, h1v = 0.f;
            if (p0 < cnt) {
                float x = cp;
                x = fmaf(smu[p0 * 3 + 0], w0, x);
                x = fmaf(smu[p0 * 3 + 1], w1, x);
                x = fmaf(smu[p0 * 3 + 2], w2v, x);
                h0 = lrelu(x);
            }
            if (p1 < cnt) {
                float x = cp;
                x = fmaf(smu[p1 * 3 + 0], w0, x);
                x = fmaf(smu[p1 * 3 + 1], w1, x);
                x = fmaf(smu[p1 * 3 + 2], w2v, x);
                h1v = lrelu(x);
            }
            h1t[k * NPAIR + i] = pack2(h0, h1v);
        }
        __syncthreads();

        // Consumer: 16 packed accumulators (32 points), FFMA2 mainloop.
        u64 acc[16];
        const u64 b2d = pack2(b2j, b2j);
#pragma unroll
        for (int g = 0; g < 16; g++) acc[g] = b2d;

#pragma unroll 4
        for (int k = 0; k < 64; k++) {
            float w;
            asm volatile("ld.shared.f32 %0, [%1];" : "=f"(w) : "r"(wb + k * 512));
            u64 wd;
            asm("mov.b64 %0, {%1, %1};" : "=l"(wd) : "f"(w));
            u32 ra = hb + k * (NPAIR * 8);
#pragma unroll
            for (int q = 0; q < 4; q++) {
                u64 x0, x1, x2, x3;
                asm volatile("ld.shared.v2.u64 {%0, %1}, [%2];"
                             : "=l"(x0), "=l"(x1) : "r"(ra + q * 32));
                asm volatile("ld.shared.v2.u64 {%0, %1}, [%2];"
                             : "=l"(x2), "=l"(x3) : "r"(ra + q * 32 + 16));
                acc[q * 4 + 0] = ffma2(x0, wd, acc[q * 4 + 0]);
                acc[q * 4 + 1] = ffma2(x1, wd, acc[q * 4 + 1]);
                acc[q * 4 + 2] = ffma2(x2, wd, acc[q * 4 + 2]);
                acc[q * 4 + 3] = ffma2(x3, wd, acc[q * 4 + 3]);
            }
        }

        // Epilogue: lrelu + masked running max.
#pragma unroll
        for (int g = 0; g < 16; g++) {
            float v0, v1;
            unpack2(acc[g], v0, v1);
            int p0 = 2 * g;
            if (p0 < cnt)     amax = fmaxf(amax, lrelu(v0));
            if (p0 + 1 < cnt) amax = fmaxf(amax, lrelu(v1));
        }
        __syncthreads();                  // h1t reused next tile
    }

    // Decision MLP: din = [gmax(128), cond(4)]
    din[j] = amax;
    if (j < 4) din[128 + j] = cond[b * 4 + j];
    __syncthreads();

    float acc3 = b3[j];
#pragma unroll 4
    for (int i = 0; i < 132; i++)
        acc3 = fmaf(din[i], W3[i * 128 + j], acc3);
    float term = lrelu(acc3) * W4[j];

#pragma unroll
    for (int o = 16; o > 0; o >>= 1)
        term += __shfl_down_sync(0xffffffffu, term, o);
    if ((j & 31) == 0) wsum[j >> 5] = term;
    __syncthreads();
    if (j == 0) out[b] = (wsum[0] + wsum[1]) + (wsum[2] + wsum[3]) + b4[0];
}

extern "C" void kernel_launch(void* const* d_in, const int* in_sizes, int n_in,
                              void* d_out, int out_size)
{
    const float* muons = (const float*)d_in[0];   // [N,3]
    const int*   bidx  = (const int*)  d_in[1];   // [N], sorted
    const float* cond  = (const float*)d_in[2];   // [B,4]

    // batch_size may appear as a device input; disambiguate by element count.
    int w = (n_in >= 12 && in_sizes[3] <= 2) ? 4 : 3;

    const float* W1 = (const float*)d_in[w + 0];
    const float* b1 = (const float*)d_in[w + 1];
    const float* W2 = (const float*)d_in[w + 2];
    const float* b2 = (const float*)d_in[w + 3];
    const float* W3 = (const float*)d_in[w + 4];
    const float* b3 = (const float*)d_in[w + 5];
    const float* W4 = (const float*)d_in[w + 6];
    const float* b4 = (const float*)d_in[w + 7];

    const int n = in_sizes[1];                    // N points
    const int B = out_size;                       // one score per batch

    segoff_kernel<<<(B + 1 + 255) / 256, 256>>>(bidx, n, B);
    critic_kernel<<<B, TPB>>>(muons, cond, W1, b1, W2, b2, W3, b3, W4, b4,
                              (float*)d_out);
}

// round 15
// speedup vs baseline: 2.3606x; 2.3606x over previous
#include <cuda_runtime.h>
#include <cstdint>

// ScalableCritic on GB300 — round 15: tensor pipe via mma.sync (HMMA).
// tcgen05 is unavailable: harness compiles through virtual arch compute_103
// (no 'a' feature set), so all tcgen05.* is rejected by ptxas. mma.sync
// m16n8k16 bf16 is baseline sm_80+ PTX and reaches the tensor units.
// (R14 never ran — broker timeout; this rev fixes a B-fragment swizzle bug
// found in audit: SWZ must apply to the FULL byte offset, not row-part only.)
//
// Layer 2 (64->128) per 32-point tile: D[j,pt] = W2^T @ h1 with bf16 split
//   D = AhBh + AlBh + AhBl   (fp32 accum; residual ~2^-18)
// Warp w owns j rows [32w,32w+32): 2 m16 tiles x 4 n8 tiles x 4 k16 steps.
// Segmented max folds into the accumulator fragments (lrelu/b2 applied after
// the max — both monotone), reduced with 2 shfl-xors.

#define TPB    128
#define TILE_N 32
#define DYN_SMEM 44032

typedef unsigned int       u32;
typedef unsigned long long u64;

__device__ int g_segoff[65537];

__global__ void segoff_kernel(const int* __restrict__ idx, int n, int B) {
    int b = blockIdx.x * blockDim.x + threadIdx.x;
    if (b > B) return;
    int lo = 0, hi = n;
    while (lo < hi) {                       // first i with idx[i] >= b
        int mid = (lo + hi) >> 1;
        if (idx[mid] < b) lo = mid + 1; else hi = mid;
    }
    g_segoff[b] = lo;
}

__device__ __forceinline__ float lrelu(float x) { return fmaxf(x, 0.2f * x); }

__device__ __forceinline__ u32 saddr(const void* p) {
    u32 a;
    asm("{.reg .u64 t; cvta.to.shared.u64 t, %1; cvt.u32.u64 %0, t;}"
        : "=r"(a) : "l"(p));
    return a;
}

#define SWZ(o) ((o) ^ (((o) >> 3) & 0x70))

// Split pair (x0,x1) into bf16 hi/lo packed words; lo captures the residual.
// cvt.rn.bf16x2.f32 d,a,b => d.hi=cvt(a), d.lo=cvt(b); we want lo=x0 (even k).
__device__ __forceinline__ void split2(float x0, float x1, u32& hp, u32& lp) {
    asm("cvt.rn.bf16x2.f32 %0, %1, %2;" : "=r"(hp) : "f"(x1), "f"(x0));
    float h0 = __uint_as_float(hp << 16);
    float h1 = __uint_as_float(hp & 0xFFFF0000u);
    asm("cvt.rn.bf16x2.f32 %0, %1, %2;" : "=r"(lp) : "f"(x1 - h1), "f"(x0 - h0));
}

__device__ __forceinline__ void ldsm4(u32* r, u32 addr) {
    asm volatile("ldmatrix.sync.aligned.m8n8.x4.shared.b16 {%0,%1,%2,%3}, [%4];"
                 : "=r"(r[0]), "=r"(r[1]), "=r"(r[2]), "=r"(r[3]) : "r"(addr));
}
__device__ __forceinline__ void ldsm2(u32* r, u32 addr) {
    asm volatile("ldmatrix.sync.aligned.m8n8.x2.shared.b16 {%0,%1}, [%2];"
                 : "=r"(r[0]), "=r"(r[1]) : "r"(addr));
}
__device__ __forceinline__ void mma16816(float* c, const u32* a, const u32* b) {
    asm volatile(
        "mma.sync.aligned.m16n8k16.row.col.f32.bf16.bf16.f32 "
        "{%0,%1,%2,%3}, {%4,%5,%6,%7}, {%8,%9}, {%0,%1,%2,%3};"
        : "+f"(c[0]), "+f"(c[1]), "+f"(c[2]), "+f"(c[3])
        : "r"(a[0]), "r"(a[1]), "r"(a[2]), "r"(a[3]), "r"(b[0]), "r"(b[1]));
}

__global__ __launch_bounds__(TPB)
void critic_kernel(const float* __restrict__ muons,
                   const float* __restrict__ cond,
                   const float* __restrict__ W1, const float* __restrict__ b1,
                   const float* __restrict__ W2, const float* __restrict__ b2,
                   const float* __restrict__ W3, const float* __restrict__ b3,
                   const float* __restrict__ W4, const float* __restrict__ b4,
                   float* __restrict__ out)
{
    extern __shared__ char dsm[];
    const u32 s0 = saddr(dsm);
    const u32 sb = (s0 + 1023u) & ~1023u;   // 1024-align for clean swizzle
    char* base = dsm + (sb - s0);

    // Layout (bytes from base): Ah 16K | Al 16K | Bh 4K | Bl 4K | aux
    const u32 oAh = 0, oAl = 16384, oBh = 32768, oBl = 36864;
    const u32 sAh = sb, sAl = sb + 16384, sBh = sb + 32768, sBl = sb + 36864;
    float4* sw14 = (float4*)(base + 40960);   // 64 x {W1r0,W1r1,W1r2,scpre}
    float*  din  = (float*) (base + 41984);   // 132
    float*  wsum = (float*) (base + 42528);   // 4

    const int b   = blockIdx.x;
    const int tid = threadIdx.x;
    const int wid = tid >> 5;
    const int lid = tid & 31;

    const float c0 = cond[b*4+0], c1 = cond[b*4+1];
    const float c2 = cond[b*4+2], c3 = cond[b*4+3];

    if (tid < 64) {
        float p = b1[tid];
        p = fmaf(c0, W1[3*64 + tid], p);
        p = fmaf(c1, W1[4*64 + tid], p);
        p = fmaf(c2, W1[5*64 + tid], p);
        p = fmaf(c3, W1[6*64 + tid], p);
        sw14[tid] = make_float4(W1[tid], W1[64 + tid], W1[128 + tid], p);
    }

    // A tiles: W2^T rows [j=tid][k 0..63] bf16 hi/lo, 128B rows, SW128.
    {
        const int j = tid;
#pragma unroll
        for (int kc = 0; kc < 8; kc++) {
            u32 hi[4], lo[4];
#pragma unroll
            for (int q = 0; q < 4; q++) {
                const int k = kc*8 + q*2;
                split2(W2[k*128 + j], W2[(k+1)*128 + j], hi[q], lo[q]);
            }
            const u32 off = SWZ((u32)(j*128 + kc*16));
            *(uint4*)(base + oAh + off) = make_uint4(hi[0], hi[1], hi[2], hi[3]);
            *(uint4*)(base + oAl + off) = make_uint4(lo[0], lo[1], lo[2], lo[3]);
        }
    }
    __syncthreads();

    const int s = g_segoff[b], e = g_segoff[b + 1];
    // rm: raw-D running max for rows jb + {lid/4, +8, +16, +24}, jb = 32*wid
    float rm[4] = {-1.0e9f, -1.0e9f, -1.0e9f, -1.0e9f};

    const int pt_local = tid >> 2;          // producer: point 0..31
    const int kg       = (tid & 3) * 16;    // producer: k-chunk base

    for (int base_pt = s; base_pt < e; base_pt += TILE_N) {
        const int cnt = min(TILE_N, e - base_pt);

        // ---- Producer: h1[pt][k] bf16 hi/lo (zeros for padded pts) ----
        {
            const bool act = pt_local < cnt;
            float m0 = 0.f, m1 = 0.f, m2 = 0.f;
            if (act) {
                const float* mp = muons + (long long)(base_pt + pt_local) * 3;
                m0 = mp[0]; m1 = mp[1]; m2 = mp[2];
            }
            u32 hi[8], lo[8];
#pragma unroll
            for (int q = 0; q < 8; q++) {
                const int k = kg + q*2;
                float x0 = 0.f, x1 = 0.f;
                if (act) {
                    const float4 v0 = sw14[k];
                    const float4 v1 = sw14[k + 1];
                    x0 = lrelu(fmaf(m0, v0.x, fmaf(m1, v0.y, fmaf(m2, v0.z, v0.w))));
                    x1 = lrelu(fmaf(m0, v1.x, fmaf(m1, v1.y, fmaf(m2, v1.z, v1.w))));
                }
                split2(x0, x1, hi[q], lo[q]);
            }
            const u32 off0 = SWZ((u32)(pt_local*128 + kg*2));
            const u32 off1 = SWZ((u32)(pt_local*128 + kg*2 + 16));
            *(uint4*)(base + oBh + off0) = make_uint4(hi[0], hi[1], hi[2], hi[3]);
            *(uint4*)(base + oBh + off1) = make_uint4(hi[4], hi[5], hi[6], hi[7]);
            *(uint4*)(base + oBl + off0) = make_uint4(lo[0], lo[1], lo[2], lo[3]);
            *(uint4*)(base + oBl + off1) = make_uint4(lo[4], lo[5], lo[6], lo[7]);
        }
        __syncthreads();

        // ---- MMA mainloop: warp owns j rows [32*wid, 32*wid+32) ----
        float acc[2][4][4];
#pragma unroll
        for (int mt = 0; mt < 2; mt++)
#pragma unroll
            for (int nt = 0; nt < 4; nt++)
#pragma unroll
                for (int i = 0; i < 4; i++) acc[mt][nt][i] = 0.f;

        const int r8 = lid & 7;
        const int jb = wid * 32;
#pragma unroll
        for (int ks = 0; ks < 4; ks++) {
            // ldmatrix x4 tile order: T00(l0-7) T10(l8-15) T01(l16-23) T11(l24-31)
            const u32 arow = (u32)(jb + r8 + 8 * ((lid >> 3) & 1));
            const u32 acol = (u32)(ks*32 + 16 * (lid >> 4));
            const u32 aoff0 = SWZ(arow * 128 + acol);          // m-tile 0
            const u32 aoff1 = SWZ((arow + 16) * 128 + acol);   // m-tile 1
            u32 Ah0[4], Ah1[4], Al0[4], Al1[4];
            ldsm4(Ah0, sAh + aoff0);  ldsm4(Ah1, sAh + aoff1);
            ldsm4(Al0, sAl + aoff0);  ldsm4(Al1, sAl + aoff1);

            const u32 bcol = (u32)(ks*32 + 16 * ((lid >> 3) & 1));
#pragma unroll
            for (int nt = 0; nt < 4; nt++) {
                const u32 boff = SWZ((u32)((nt*8 + r8) * 128) + bcol
                                     ^ ((((u32)((nt*8 + r8) * 128)) >> 3) & 0x70)
                                     ^ ((((u32)((nt*8 + r8) * 128)) >> 3) & 0x70));
                // NOTE: expression above simplifies to SWZ(row*128+bcol); keep
                // the canonical full-offset form below for clarity:
                const u32 boff_full = SWZ((u32)((nt*8 + r8) * 128) + bcol);
                (void)boff;
                u32 Bh[2], Bl[2];
                ldsm2(Bh, sBh + boff_full);
                ldsm2(Bl, sBl + boff_full);
                mma16816(acc[0][nt], Ah0, Bh);
                mma16816(acc[1][nt], Ah1, Bh);
                mma16816(acc[0][nt], Al0, Bh);
                mma16816(acc[1][nt], Al1, Bh);
                mma16816(acc[0][nt], Ah0, Bl);
                mma16816(acc[1][nt], Ah1, Bl);
            }
        }

        // ---- Epilogue: masked max into rm (c0,c1 row g; c2,c3 row g+8) ----
        const int tg = lid & 3;
#pragma unroll
        for (int nt = 0; nt < 4; nt++) {
            const int pt0 = nt*8 + 2*tg;
            if (pt0 < cnt) {
                rm[0] = fmaxf(rm[0], acc[0][nt][0]);
                rm[1] = fmaxf(rm[1], acc[0][nt][2]);
                rm[2] = fmaxf(rm[2], acc[1][nt][0]);
                rm[3] = fmaxf(rm[3], acc[1][nt][2]);
            }
            if (pt0 + 1 < cnt) {
                rm[0] = fmaxf(rm[0], acc[0][nt][1]);
                rm[1] = fmaxf(rm[1], acc[0][nt][3]);
                rm[2] = fmaxf(rm[2], acc[1][nt][1]);
                rm[3] = fmaxf(rm[3], acc[1][nt][3]);
            }
        }
        __syncthreads();                    // B tiles reused next iteration
    }

    // Cross-lane combine over the 4-lane column group.
#pragma unroll
    for (int i = 0; i < 4; i++) {
        rm[i] = fmaxf(rm[i], __shfl_xor_sync(0xffffffffu, rm[i], 1));
        rm[i] = fmaxf(rm[i], __shfl_xor_sync(0xffffffffu, rm[i], 2));
    }
    if ((lid & 3) == 0) {
        const int  jr  = wid*32 + (lid >> 2);
        const bool has = (e > s);
        din[jr]      = has ? lrelu(rm[0] + b2[jr])      : -1.0e9f;
        din[jr + 8]  = has ? lrelu(rm[1] + b2[jr + 8])  : -1.0e9f;
        din[jr + 16] = has ? lrelu(rm[2] + b2[jr + 16]) : -1.0e9f;
        din[jr + 24] = has ? lrelu(rm[3] + b2[jr + 24]) : -1.0e9f;
    }
    if (tid < 4) din[128 + tid] = cond[b*4 + tid];
    __syncthreads();

    // Decision MLP.
    float acc3 = b3[tid];
#pragma unroll 4
    for (int i = 0; i < 132; i++)
        acc3 = fmaf(din[i], W3[i*128 + tid], acc3);
    float term = lrelu(acc3) * W4[tid];
#pragma unroll
    for (int o = 16; o > 0; o >>= 1)
        term += __shfl_down_sync(0xffffffffu, term, o);
    if (lid == 0) wsum[wid] = term;
    __syncthreads();
    if (tid == 0) out[b] = (wsum[0] + wsum[1]) + (wsum[2] + wsum[3]) + b4[0];
}

extern "C" void kernel_launch(void* const* d_in, const int* in_sizes, int n_in,
                              void* d_out, int out_size)
{
    const float* muons = (const float*)d_in[0];   // [N,3]
    const int*   bidx  = (const int*)  d_in[1];   // [N], sorted
    const float* cond  = (const float*)d_in[2];   // [B,4]

    // batch_size may appear as a device input; disambiguate by element count.
    int w = (n_in >= 12 && in_sizes[3] <= 2) ? 4 : 3;

    const float* W1 = (const float*)d_in[w + 0];
    const float* b1 = (const float*)d_in[w + 1];
    const float* W2 = (const float*)d_in[w + 2];
    const float* b2 = (const float*)d_in[w + 3];
    const float* W3 = (const float*)d_in[w + 4];
    const float* b3 = (const float*)d_in[w + 5];
    const float* W4 = (const float*)d_in[w + 6];
    const float* b4 = (const float*)d_in[w + 7];

    const int n = in_sizes[1];                    // N points
    const int B = out_size;                       // one score per batch

    segoff_kernel<<<(B + 1 + 255) / 256, 256>>>(bidx, n, B);
    critic_kernel<<<B, TPB, DYN_SMEM>>>(muons, cond, W1, b1, W2, b2, W3, b3,
                                        W4, b4, (float*)d_out);
}